// round 14
// baseline (speedup 1.0000x reference)
#include <cuda_runtime.h>
#include <cuda_bf16.h>
#include <cstdint>

// R14: HMMA bf16 hi/lo-split DGM.
// vs R13: 4 warps/CTA with m32n64 warp tiles (-25% LDSM traffic: wf/HMMA
// 1.33 -> 1.0), W streamed in 32-k chunked double buffers (41KB instead of
// 139KB) -> SMEM 108KB/CTA -> 2 CTAs/SM (same 8 warps/SM, two independent
// streams). Layer order R,Z,G,H with G parked in the dead S tile region to
// keep registers ~190 (2 CTAs need <=256/thread).

namespace {
constexpr int XD   = 100;
constexpr int HID  = 128;
constexpr int TM   = 64;
constexpr int NTHR = 128;           // 4 warps: wm=warp>>1, wn=warp&1
constexpr int NBLK = 4096;          // 262144 / TM

constexpr int LDT    = 272;         // S/SR tile row stride (136 bf16)
constexpr int S_TILE = 64 * LDT;    // 17408
constexpr int OFF_S  = 0;           // S hi | lo (34816)
constexpr int OFF_SR = 2 * S_TILE;  // SR / XT hi | lo (34816)
constexpr int OFF_W  = 4 * S_TILE;  // 69632: 2 chunk buffers
constexpr int W_CHUNK = 256 * 80;   // 20480: [hi 128 rows | lo 128 rows] x 80B
constexpr int SMEM_TOTAL = OFF_W + 2 * W_CHUNK;  // 110592
}

// weight images: [mat][hi|lo][n][k 0..135] bf16 row-major.
// 0 Sw, 1 Uz, 2 Ug, 3 Ur, 4 Uh, 5 Wsz, 6 Wsg, 7 Wsr, 8 Wsh
__device__ __align__(16) unsigned short g_w[9][2][128][136];
// u planes (z,g,r,h), bias-folded fp32: [blk][plane][row][col]
__device__ float g_u[(size_t)NBLK * 4 * TM * HID];

__device__ __forceinline__ uint32_t smem_u32(const void* p) {
    uint32_t a;
    asm("{ .reg .u64 t; cvta.to.shared.u64 t, %1; cvt.u32.u64 %0, t; }"
        : "=r"(a) : "l"(p));
    return a;
}
__device__ __forceinline__ float bf2f(uint32_t u) {
    return __bfloat162float(__ushort_as_bfloat16((unsigned short)u));
}
__device__ __forceinline__ uint32_t f2bf2(float lo, float hi) {
    uint32_t r;
    asm("cvt.rn.bf16x2.f32 %0, %1, %2;" : "=r"(r) : "f"(hi), "f"(lo));
    return r;
}
__device__ __forceinline__ void store_split(char* base, uint32_t off,
                                            float v0, float v1) {
    uint32_t hp = f2bf2(v0, v1);
    *(uint32_t*)(base + off) = hp;
    *(uint32_t*)(base + S_TILE + off) =
        f2bf2(v0 - bf2f(hp & 0xffffu), v1 - bf2f(hp >> 16));
}
__device__ __forceinline__ float2 ld_pair(const char* base, uint32_t off) {
    uint32_t h = *(const uint32_t*)(base + off);
    uint32_t l = *(const uint32_t*)(base + S_TILE + off);
    return make_float2(bf2f(h & 0xffffu) + bf2f(l & 0xffffu),
                       bf2f(h >> 16) + bf2f(l >> 16));
}
__device__ __forceinline__ float fast_tanh(float v) {
    float e = __expf(2.0f * v);
    return 1.0f - __fdividef(2.0f, e + 1.0f);
}
__device__ __forceinline__ void ldsm4(uint32_t* r, uint32_t a) {
    asm volatile("ldmatrix.sync.aligned.m8n8.x4.shared.b16 {%0,%1,%2,%3}, [%4];"
                 : "=r"(r[0]), "=r"(r[1]), "=r"(r[2]), "=r"(r[3]) : "r"(a));
}
__device__ __forceinline__ void mma16816(float* d, const uint32_t* a,
                                         const uint32_t* b) {
    asm volatile(
        "mma.sync.aligned.m16n8k16.row.col.f32.bf16.bf16.f32 "
        "{%0,%1,%2,%3}, {%4,%5,%6,%7}, {%8,%9}, {%0,%1,%2,%3};"
        : "+f"(d[0]), "+f"(d[1]), "+f"(d[2]), "+f"(d[3])
        : "r"(a[0]), "r"(a[1]), "r"(a[2]), "r"(a[3]), "r"(b[0]), "r"(b[1]));
}

__global__ void prep_weights(const float* Sw, const float* Uz, const float* Ug,
                             const float* Ur, const float* Uh, const float* Wsz,
                             const float* Wsg, const float* Wsr, const float* Wsh) {
    int m = blockIdx.x;
    const float* src;
    int Ks;
    switch (m) {
        case 0: src = Sw;  Ks = 101; break;
        case 1: src = Uz;  Ks = 101; break;
        case 2: src = Ug;  Ks = 101; break;
        case 3: src = Ur;  Ks = 101; break;
        case 4: src = Uh;  Ks = 101; break;
        case 5: src = Wsz; Ks = 128; break;
        case 6: src = Wsg; Ks = 128; break;
        case 7: src = Wsr; Ks = 128; break;
        default: src = Wsh; Ks = 128; break;
    }
    for (int idx = threadIdx.x; idx < 128 * 136; idx += blockDim.x) {
        int n = idx / 136, k = idx - n * 136;
        float v = (k < Ks) ? src[(size_t)k * HID + n] : 0.0f;  // Bt[n][k]
        __nv_bfloat16 h = __float2bfloat16(v);
        g_w[m][0][n][k] = __bfloat16_as_ushort(h);
        g_w[m][1][n][k] =
            __bfloat16_as_ushort(__float2bfloat16(v - __bfloat162float(h)));
    }
}

// copy k-slice [k0, k0+kc) (kc = 32 or 16) of gate `mat` (hi then lo rows)
// into chunk buffer at sb. Row stride 80B in smem (conflict-free for ldsm).
__device__ __forceinline__ void cp_chunkW(uint32_t sb, int mat, int k0, int kc,
                                          int tid) {
    const char* src = (const char*)g_w[mat];
    if (kc == 32) {
        // 256 rows x 4 segs of 16B
#pragma unroll 2
        for (int u = tid; u < 1024; u += NTHR) {
            int row = u >> 2, seg = u & 3;
            asm volatile("cp.async.cg.shared.global [%0], [%1], 16;"
                         :: "r"(sb + row * 80 + seg * 16),
                            "l"(src + (size_t)row * 272 + k0 * 2 + seg * 16)
                         : "memory");
        }
    } else {
        // 256 rows x 2 segs of 16B
#pragma unroll 2
        for (int u = tid; u < 512; u += NTHR) {
            int row = u >> 1, seg = u & 1;
            asm volatile("cp.async.cg.shared.global [%0], [%1], 16;"
                         :: "r"(sb + row * 80 + seg * 16),
                            "l"(src + (size_t)row * 272 + k0 * 2 + seg * 16)
                         : "memory");
        }
    }
    asm volatile("cp.async.commit_group;" ::: "memory");
}

// acc[nt*2+mf][4]: warp tile m32 x n64 over K = KK*16, W streamed in 32-k
// chunks (double buffered). Contains __syncthreads -> call uniformly.
template <int KK>
__device__ __forceinline__ void gemm_chunked(uint32_t sbase, int mat,
                                             uint32_t aHi0, uint32_t aHi1,
                                             uint32_t bBase, int tid,
                                             float acc[16][4]) {
    constexpr int K = KK * 16;
    constexpr int CH = (K + 31) / 32;
#pragma unroll
    for (int i = 0; i < 16; ++i) {
        acc[i][0] = 0.f; acc[i][1] = 0.f; acc[i][2] = 0.f; acc[i][3] = 0.f;
    }
    cp_chunkW(sbase + OFF_W, mat, 0, (K < 32 ? K : 32), tid);
#pragma unroll
    for (int ch = 0; ch < CH; ++ch) {
        asm volatile("cp.async.wait_group 0;" ::: "memory");
        __syncthreads();
        if (ch + 1 < CH) {
            const int nk0 = (ch + 1) * 32;
            cp_chunkW(sbase + OFF_W + ((ch + 1) & 1) * W_CHUNK, mat, nk0,
                      (K - nk0 < 32 ? K - nk0 : 32), tid);
        }
        const uint32_t wb = sbase + OFF_W + (ch & 1) * W_CHUNK + bBase;
        const int kkc = (KK - ch * 2 < 2) ? (KK - ch * 2) : 2;
#pragma unroll
        for (int kkl = 0; kkl < 2; ++kkl) {
            if (kkl >= kkc) break;
            const uint32_t ka = (ch * 32 + kkl * 16) * 2;
            uint32_t ah0[4], al0[4], ah1[4], al1[4];
            ldsm4(ah0, aHi0 + ka);
            ldsm4(al0, aHi0 + ka + S_TILE);
            ldsm4(ah1, aHi1 + ka);
            ldsm4(al1, aHi1 + ka + S_TILE);
#pragma unroll
            for (int nt = 0; nt < 8; ++nt) {
                uint32_t b[4];
                ldsm4(b, wb + nt * 640 + kkl * 32);
                mma16816(acc[nt * 2 + 0], ah0, b);
                mma16816(acc[nt * 2 + 0], ah0, b + 2);
                mma16816(acc[nt * 2 + 0], al0, b);
                mma16816(acc[nt * 2 + 1], ah1, b);
                mma16816(acc[nt * 2 + 1], ah1, b + 2);
                mma16816(acc[nt * 2 + 1], al1, b);
            }
        }
    }
}

__global__ void __launch_bounds__(NTHR, 2) dgm_mma_kernel(
    const float* __restrict__ x, const float* __restrict__ t,
    const float* __restrict__ Sw_b,
    const float* __restrict__ Uz_b, const float* __restrict__ Wsz_b,
    const float* __restrict__ Ug_b, const float* __restrict__ Wsg_b,
    const float* __restrict__ Ur_b, const float* __restrict__ Wsr_b,
    const float* __restrict__ Uh_b, const float* __restrict__ Wsh_b,
    const float* __restrict__ Wf_w, const float* __restrict__ Wf_b,
    const int* __restrict__ n_layers_p, float* __restrict__ out) {
    extern __shared__ char smem[];
    const int tid = threadIdx.x;
    const int lane = tid & 31;
    const int warp = tid >> 5;
    const int wm = warp >> 1;   // 0..1 (m32 group)
    const int wn = warp & 1;    // 0..1 (n64 group)
    const int row0 = blockIdx.x * TM;
    const uint32_t sbase = smem_u32(smem);

    // A ldmatrix lane addresses (hi; lo at +S_TILE)
    const uint32_t aS0 =
        sbase + OFF_S + (wm * 32 + (lane & 15)) * LDT + ((lane >> 4) << 4);
    const uint32_t aS1 = aS0 + 16 * LDT;
    const uint32_t aSR0 = aS0 + (OFF_SR - OFF_S);
    const uint32_t aSR1 = aSR0 + 16 * LDT;
    // B lane offset within a W chunk buffer (hi rows 0-127, lo rows 128-255)
    const uint32_t bBase = (wn * 64 + (lane & 7)) * 80 +
                           (((lane >> 3) & 1) << 4) +
                           ((lane & 16) ? 128 * 80 : 0);

    // epilogue fragment coords: rows r+{0,8}, r = wm*32 + mf*16 + (lane>>2)
    const int er = wm * 32 + (lane >> 2);
    const int ecq = (lane & 3) * 2;

    // ---- build XT tiles (hi|lo) in SR region ----
    {
        char* xh = smem + OFF_SR;
        const float4* x4 = reinterpret_cast<const float4*>(x);
        for (int idx = tid; idx < TM * 25; idx += NTHR) {
            int m = idx / 25, q = idx - m * 25;
            float4 v = x4[(size_t)(row0 + m) * 25 + q];
            float vv[4] = {v.x, v.y, v.z, v.w};
#pragma unroll
            for (int j = 0; j < 4; ++j) {
                uint32_t off = m * LDT + (q * 4 + j) * 2;
                __nv_bfloat16 h = __float2bfloat16(vv[j]);
                *(__nv_bfloat16*)(xh + off) = h;
                *(__nv_bfloat16*)(xh + S_TILE + off) =
                    __float2bfloat16(vv[j] - __bfloat162float(h));
            }
        }
        if (tid < TM) {
            float tv = t[row0 + tid];
            uint32_t off = tid * LDT + 100 * 2;
            __nv_bfloat16 h = __float2bfloat16(tv);
            *(__nv_bfloat16*)(xh + off) = h;
            *(__nv_bfloat16*)(xh + S_TILE + off) =
                __float2bfloat16(tv - __bfloat162float(h));
            for (int k = 101; k < 112; ++k) {
                uint32_t o = tid * LDT + k * 2;
                *(unsigned short*)(xh + o) = 0;
                *(unsigned short*)(xh + S_TILE + o) = 0;
            }
        }
    }
    // (gemm's internal first sync orders the XT writes)

    float acc[16][4];

    // ---- S1 = tanh(xt @ SwT + Sw_b) -> S tiles ----
    gemm_chunked<7>(sbase, 0, aSR0, aSR1, bBase, tid, acc);
#pragma unroll
    for (int nt = 0; nt < 8; ++nt)
#pragma unroll
        for (int mf = 0; mf < 2; ++mf) {
            int c = wn * 64 + nt * 8 + ecq;
            float2 b = __ldg((const float2*)(Sw_b + c));
            uint32_t o0 = (er + mf * 16) * LDT + c * 2, o1 = o0 + 8 * LDT;
            float* a = acc[nt * 2 + mf];
            store_split(smem + OFF_S, o0, fast_tanh(a[0] + b.x),
                        fast_tanh(a[1] + b.y));
            store_split(smem + OFF_S, o1, fast_tanh(a[2] + b.x),
                        fast_tanh(a[3] + b.y));
        }

    // ---- u planes (bias-folded) -> g_u ----
#pragma unroll 1
    for (int pl = 0; pl < 4; ++pl) {
        gemm_chunked<7>(sbase, pl + 1, aSR0, aSR1, bBase, tid, acc);
        const float *b1p, *b2p;
        if (pl == 0)      { b1p = Uz_b; b2p = Wsz_b; }
        else if (pl == 1) { b1p = Ug_b; b2p = Wsg_b; }
        else if (pl == 2) { b1p = Ur_b; b2p = Wsr_b; }
        else              { b1p = Uh_b; b2p = Wsh_b; }
        float* uP = g_u + ((size_t)blockIdx.x * 4 + pl) * TM * HID;
#pragma unroll
        for (int nt = 0; nt < 8; ++nt)
#pragma unroll
            for (int mf = 0; mf < 2; ++mf) {
                int r = er + mf * 16, c = wn * 64 + nt * 8 + ecq;
                float2 b1 = __ldg((const float2*)(b1p + c));
                float2 b2 = __ldg((const float2*)(b2p + c));
                float* a = acc[nt * 2 + mf];
                *(float2*)(uP + r * HID + c) =
                    make_float2(a[0] + b1.x + b2.x, a[1] + b1.y + b2.y);
                *(float2*)(uP + (r + 8) * HID + c) =
                    make_float2(a[2] + b1.x + b2.x, a[3] + b1.y + b2.y);
            }
    }

    const int nl = *n_layers_p;
    const float* uZ = g_u + ((size_t)blockIdx.x * 4 + 0) * TM * HID;
    const float* uG = g_u + ((size_t)blockIdx.x * 4 + 1) * TM * HID;
    const float* uR = g_u + ((size_t)blockIdx.x * 4 + 2) * TM * HID;
    const float* uH = g_u + ((size_t)blockIdx.x * 4 + 3) * TM * HID;

    float zs[16][4];

#pragma unroll 1
    for (int l = 1; l < nl; ++l) {
        // ---- R: SR = S * tanh(uR + S@WsrT) ----
        gemm_chunked<8>(sbase, 7, aS0, aS1, bBase, tid, acc);
#pragma unroll
        for (int nt = 0; nt < 8; ++nt)
#pragma unroll
            for (int mf = 0; mf < 2; ++mf) {
                int r = er + mf * 16, c = wn * 64 + nt * 8 + ecq;
                float2 u0 = *(const float2*)(uR + r * HID + c);
                float2 u1 = *(const float2*)(uR + (r + 8) * HID + c);
                uint32_t o0 = r * LDT + c * 2, o1 = o0 + 8 * LDT;
                float2 s0 = ld_pair(smem + OFF_S, o0);
                float2 s1 = ld_pair(smem + OFF_S, o1);
                float* a = acc[nt * 2 + mf];
                store_split(smem + OFF_SR, o0, s0.x * fast_tanh(a[0] + u0.x),
                            s0.y * fast_tanh(a[1] + u0.y));
                store_split(smem + OFF_SR, o1, s1.x * fast_tanh(a[2] + u1.x),
                            s1.y * fast_tanh(a[3] + u1.y));
            }

        // ---- Z: zs = tanh(uZ + S@WszT) * S (registers) ----
        gemm_chunked<8>(sbase, 5, aS0, aS1, bBase, tid, acc);
#pragma unroll
        for (int nt = 0; nt < 8; ++nt)
#pragma unroll
            for (int mf = 0; mf < 2; ++mf) {
                int r = er + mf * 16, c = wn * 64 + nt * 8 + ecq;
                float2 u0 = *(const float2*)(uZ + r * HID + c);
                float2 u1 = *(const float2*)(uZ + (r + 8) * HID + c);
                uint32_t o0 = r * LDT + c * 2, o1 = o0 + 8 * LDT;
                float2 s0 = ld_pair(smem + OFF_S, o0);
                float2 s1 = ld_pair(smem + OFF_S, o1);
                float* a = acc[nt * 2 + mf];
                float* z = zs[nt * 2 + mf];
                z[0] = fast_tanh(a[0] + u0.x) * s0.x;
                z[1] = fast_tanh(a[1] + u0.y) * s0.y;
                z[2] = fast_tanh(a[2] + u1.x) * s1.x;
                z[3] = fast_tanh(a[3] + u1.y) * s1.y;
            }

        // ---- G: G = tanh(uG + S@WsgT) -> parked in (now dead) S tiles ----
        gemm_chunked<8>(sbase, 6, aS0, aS1, bBase, tid, acc);
        __syncthreads();  // all warps done reading S before overwriting
#pragma unroll
        for (int nt = 0; nt < 8; ++nt)
#pragma unroll
            for (int mf = 0; mf < 2; ++mf) {
                int r = er + mf * 16, c = wn * 64 + nt * 8 + ecq;
                float2 u0 = *(const float2*)(uG + r * HID + c);
                float2 u1 = *(const float2*)(uG + (r + 8) * HID + c);
                uint32_t o0 = r * LDT + c * 2, o1 = o0 + 8 * LDT;
                float* a = acc[nt * 2 + mf];
                store_split(smem + OFF_S, o0, fast_tanh(a[0] + u0.x),
                            fast_tanh(a[1] + u0.y));
                store_split(smem + OFF_S, o1, fast_tanh(a[2] + u1.x),
                            fast_tanh(a[3] + u1.y));
            }

        // ---- H: S_new = (1-G)*(uH + SR@WshT) + zs -> S tiles (own cells) ----
        gemm_chunked<8>(sbase, 8, aSR0, aSR1, bBase, tid, acc);
#pragma unroll
        for (int nt = 0; nt < 8; ++nt)
#pragma unroll
            for (int mf = 0; mf < 2; ++mf) {
                int r = er + mf * 16, c = wn * 64 + nt * 8 + ecq;
                float2 u0 = *(const float2*)(uH + r * HID + c);
                float2 u1 = *(const float2*)(uH + (r + 8) * HID + c);
                uint32_t o0 = r * LDT + c * 2, o1 = o0 + 8 * LDT;
                float2 g0 = ld_pair(smem + OFF_S, o0);
                float2 g1 = ld_pair(smem + OFF_S, o1);
                float* a = acc[nt * 2 + mf];
                float* z = zs[nt * 2 + mf];
                store_split(smem + OFF_S, o0,
                            (1.0f - g0.x) * (a[0] + u0.x) + z[0],
                            (1.0f - g0.y) * (a[1] + u0.y) + z[1]);
                store_split(smem + OFF_S, o1,
                            (1.0f - g1.x) * (a[2] + u1.x) + z[2],
                            (1.0f - g1.y) * (a[3] + u1.y) + z[3]);
            }
        // next gemm's internal first sync orders these writes
    }

    // ---- final: out = S @ Wf + bf (2 threads per row) ----
    __syncthreads();
    {
        const int orow = tid >> 1, q = tid & 1;
        float s = 0.0f;
#pragma unroll 8
        for (int cc = 0; cc < 32; ++cc) {
            int col = q * 64 + cc * 2;
            float2 sv = ld_pair(smem + OFF_S, orow * LDT + col * 2);
            float2 wf = __ldg((const float2*)(Wf_w + col));
            s += sv.x * wf.x + sv.y * wf.y;
        }
        s += __shfl_xor_sync(0xFFFFFFFFu, s, 1);
        if (q == 0) out[row0 + orow] = s + Wf_b[0];
    }
}

extern "C" void kernel_launch(void* const* d_in, const int* in_sizes, int n_in,
                              void* d_out, int out_size) {
    const float* x     = (const float*)d_in[0];
    const float* t     = (const float*)d_in[1];
    const float* Sw_w  = (const float*)d_in[2];
    const float* Sw_b  = (const float*)d_in[3];
    const float* Uz_w  = (const float*)d_in[4];
    const float* Uz_b  = (const float*)d_in[5];
    const float* Wsz_w = (const float*)d_in[6];
    const float* Wsz_b = (const float*)d_in[7];
    const float* Ug_w  = (const float*)d_in[8];
    const float* Ug_b  = (const float*)d_in[9];
    const float* Wsg_w = (const float*)d_in[10];
    const float* Wsg_b = (const float*)d_in[11];
    const float* Ur_w  = (const float*)d_in[12];
    const float* Ur_b  = (const float*)d_in[13];
    const float* Wsr_w = (const float*)d_in[14];
    const float* Wsr_b = (const float*)d_in[15];
    const float* Uh_w  = (const float*)d_in[16];
    const float* Uh_b  = (const float*)d_in[17];
    const float* Wsh_w = (const float*)d_in[18];
    const float* Wsh_b = (const float*)d_in[19];
    const float* Wf_w  = (const float*)d_in[20];
    const float* Wf_b  = (const float*)d_in[21];
    const int*   nlp   = (const int*)d_in[22];
    float* out = (float*)d_out;

    static bool attr_set = false;
    if (!attr_set) {
        cudaFuncSetAttribute(dgm_mma_kernel,
                             cudaFuncAttributeMaxDynamicSharedMemorySize,
                             SMEM_TOTAL);
        attr_set = true;
    }
    prep_weights<<<9, 256>>>(Sw_w, Uz_w, Ug_w, Ur_w, Uh_w,
                             Wsz_w, Wsg_w, Wsr_w, Wsh_w);
    dgm_mma_kernel<<<NBLK, NTHR, SMEM_TOTAL>>>(
        x, t, Sw_b, Uz_b, Wsz_b, Ug_b, Wsg_b, Ur_b, Wsr_b, Uh_b, Wsh_b,
        Wf_w, Wf_b, nlp, out);
}

// round 15
// speedup vs baseline: 1.0378x; 1.0378x over previous
#include <cuda_runtime.h>
#include <cuda_bf16.h>
#include <cstdint>

// R15: HMMA bf16 hi/lo-split DGM = R13 warp tiling (8 warps, m32n32)
//      + R14 occupancy trick (32-k chunked W double-buffer, 41KB).
// SMEM 108KB/CTA -> 2 CTAs/SM -> 16 warps/SM (R13 had 8, latency-limited).
// Registers held <=128 via launch_bounds(256,2): acc 32 + zs 32, G parked
// in the dead S tiles (R14-validated), no spills (R14's 254-reg mistake).

namespace {
constexpr int XD   = 100;
constexpr int HID  = 128;
constexpr int TM   = 64;
constexpr int NTHR = 256;           // 8 warps: wm=warp>>2 (m32), wn=warp&3 (n32)
constexpr int NBLK = 4096;          // 262144 / TM

constexpr int LDT    = 272;         // S/SR tile row stride (136 bf16)
constexpr int S_TILE = 64 * LDT;    // 17408
constexpr int OFF_S  = 0;           // S hi | lo (34816)
constexpr int OFF_SR = 2 * S_TILE;  // SR / XT hi | lo (34816)
constexpr int OFF_W  = 4 * S_TILE;  // 69632: 2 chunk buffers
constexpr int W_CHUNK = 256 * 80;   // 20480: [hi 128 n-rows | lo 128] x 80B
constexpr int SMEM_TOTAL = OFF_W + 2 * W_CHUNK;  // 110592 <= 113664 (2/SM)
}

// weight images: [mat][hi|lo][n][k 0..135] bf16 row-major.
// 0 Sw, 1 Uz, 2 Ug, 3 Ur, 4 Uh, 5 Wsz, 6 Wsg, 7 Wsr, 8 Wsh
__device__ __align__(16) unsigned short g_w[9][2][128][136];
// u planes (z,g,r,h), bias-folded fp32: [blk][plane][row][col]
__device__ float g_u[(size_t)NBLK * 4 * TM * HID];

__device__ __forceinline__ uint32_t smem_u32(const void* p) {
    uint32_t a;
    asm("{ .reg .u64 t; cvta.to.shared.u64 t, %1; cvt.u32.u64 %0, t; }"
        : "=r"(a) : "l"(p));
    return a;
}
__device__ __forceinline__ float bf2f(uint32_t u) {
    return __bfloat162float(__ushort_as_bfloat16((unsigned short)u));
}
__device__ __forceinline__ uint32_t f2bf2(float lo, float hi) {
    uint32_t r;
    asm("cvt.rn.bf16x2.f32 %0, %1, %2;" : "=r"(r) : "f"(hi), "f"(lo));
    return r;
}
__device__ __forceinline__ void store_split(char* base, uint32_t off,
                                            float v0, float v1) {
    uint32_t hp = f2bf2(v0, v1);
    *(uint32_t*)(base + off) = hp;
    *(uint32_t*)(base + S_TILE + off) =
        f2bf2(v0 - bf2f(hp & 0xffffu), v1 - bf2f(hp >> 16));
}
__device__ __forceinline__ float2 ld_pair(const char* base, uint32_t off) {
    uint32_t h = *(const uint32_t*)(base + off);
    uint32_t l = *(const uint32_t*)(base + S_TILE + off);
    return make_float2(bf2f(h & 0xffffu) + bf2f(l & 0xffffu),
                       bf2f(h >> 16) + bf2f(l >> 16));
}
__device__ __forceinline__ float fast_tanh(float v) {
    float e = __expf(2.0f * v);
    return 1.0f - __fdividef(2.0f, e + 1.0f);
}
__device__ __forceinline__ void ldsm4(uint32_t* r, uint32_t a) {
    asm volatile("ldmatrix.sync.aligned.m8n8.x4.shared.b16 {%0,%1,%2,%3}, [%4];"
                 : "=r"(r[0]), "=r"(r[1]), "=r"(r[2]), "=r"(r[3]) : "r"(a));
}
__device__ __forceinline__ void mma16816(float* d, const uint32_t* a,
                                         const uint32_t* b) {
    asm volatile(
        "mma.sync.aligned.m16n8k16.row.col.f32.bf16.bf16.f32 "
        "{%0,%1,%2,%3}, {%4,%5,%6,%7}, {%8,%9}, {%0,%1,%2,%3};"
        : "+f"(d[0]), "+f"(d[1]), "+f"(d[2]), "+f"(d[3])
        : "r"(a[0]), "r"(a[1]), "r"(a[2]), "r"(a[3]), "r"(b[0]), "r"(b[1]));
}

__global__ void prep_weights(const float* Sw, const float* Uz, const float* Ug,
                             const float* Ur, const float* Uh, const float* Wsz,
                             const float* Wsg, const float* Wsr, const float* Wsh) {
    int m = blockIdx.x;
    const float* src;
    int Ks;
    switch (m) {
        case 0: src = Sw;  Ks = 101; break;
        case 1: src = Uz;  Ks = 101; break;
        case 2: src = Ug;  Ks = 101; break;
        case 3: src = Ur;  Ks = 101; break;
        case 4: src = Uh;  Ks = 101; break;
        case 5: src = Wsz; Ks = 128; break;
        case 6: src = Wsg; Ks = 128; break;
        case 7: src = Wsr; Ks = 128; break;
        default: src = Wsh; Ks = 128; break;
    }
    for (int idx = threadIdx.x; idx < 128 * 136; idx += blockDim.x) {
        int n = idx / 136, k = idx - n * 136;
        float v = (k < Ks) ? src[(size_t)k * HID + n] : 0.0f;  // Bt[n][k]
        __nv_bfloat16 h = __float2bfloat16(v);
        g_w[m][0][n][k] = __bfloat16_as_ushort(h);
        g_w[m][1][n][k] =
            __bfloat16_as_ushort(__float2bfloat16(v - __bfloat162float(h)));
    }
}

// copy k-slice [k0, k0+kc) (kc = 32 or 16) of gate `mat` (hi rows 0-127,
// lo rows 128-255) into chunk buffer at sb; smem row stride 80B.
__device__ __forceinline__ void cp_chunkW(uint32_t sb, int mat, int k0, int kc,
                                          int tid) {
    const char* src = (const char*)g_w[mat];
    if (kc == 32) {
#pragma unroll
        for (int u = tid; u < 1024; u += NTHR) {
            int row = u >> 2, seg = u & 3;
            asm volatile("cp.async.cg.shared.global [%0], [%1], 16;"
                         :: "r"(sb + row * 80 + seg * 16),
                            "l"(src + (size_t)row * 272 + k0 * 2 + seg * 16)
                         : "memory");
        }
    } else {
#pragma unroll
        for (int u = tid; u < 512; u += NTHR) {
            int row = u >> 1, seg = u & 1;
            asm volatile("cp.async.cg.shared.global [%0], [%1], 16;"
                         :: "r"(sb + row * 80 + seg * 16),
                            "l"(src + (size_t)row * 272 + k0 * 2 + seg * 16)
                         : "memory");
        }
    }
    asm volatile("cp.async.commit_group;" ::: "memory");
}

// acc[nt*2+mf][4]: warp tile m32 x n32 over K = KK*16; W streamed in 32-k
// chunks (double buffered). Contains __syncthreads -> call uniformly.
template <int KK>
__device__ __forceinline__ void gemm_chunked(uint32_t sbase, int mat,
                                             uint32_t aHi0, uint32_t aHi1,
                                             uint32_t bBase, int tid,
                                             float acc[8][4]) {
    constexpr int K = KK * 16;
    constexpr int CH = (K + 31) / 32;
#pragma unroll
    for (int i = 0; i < 8; ++i) {
        acc[i][0] = 0.f; acc[i][1] = 0.f; acc[i][2] = 0.f; acc[i][3] = 0.f;
    }
    cp_chunkW(sbase + OFF_W, mat, 0, (K < 32 ? K : 32), tid);
#pragma unroll
    for (int ch = 0; ch < CH; ++ch) {
        asm volatile("cp.async.wait_group 0;" ::: "memory");
        __syncthreads();
        if (ch + 1 < CH) {
            const int nk0 = (ch + 1) * 32;
            cp_chunkW(sbase + OFF_W + ((ch + 1) & 1) * W_CHUNK, mat, nk0,
                      (K - nk0 < 32 ? K - nk0 : 32), tid);
        }
        const uint32_t wb = sbase + OFF_W + (ch & 1) * W_CHUNK + bBase;
        const int kkc = (KK - ch * 2 < 2) ? (KK - ch * 2) : 2;
#pragma unroll
        for (int kkl = 0; kkl < 2; ++kkl) {
            if (kkl >= kkc) break;
            const uint32_t ka = (ch * 32 + kkl * 16) * 2;
            uint32_t ah0[4], al0[4], ah1[4], al1[4];
            ldsm4(ah0, aHi0 + ka);
            ldsm4(al0, aHi0 + ka + S_TILE);
            ldsm4(ah1, aHi1 + ka);
            ldsm4(al1, aHi1 + ka + S_TILE);
#pragma unroll
            for (int nt = 0; nt < 4; ++nt) {
                uint32_t b[4];
                ldsm4(b, wb + nt * 640 + kkl * 32);
                mma16816(acc[nt * 2 + 0], ah0, b);
                mma16816(acc[nt * 2 + 0], ah0, b + 2);
                mma16816(acc[nt * 2 + 0], al0, b);
                mma16816(acc[nt * 2 + 1], ah1, b);
                mma16816(acc[nt * 2 + 1], ah1, b + 2);
                mma16816(acc[nt * 2 + 1], al1, b);
            }
        }
    }
}

__global__ void __launch_bounds__(NTHR, 2) dgm_mma_kernel(
    const float* __restrict__ x, const float* __restrict__ t,
    const float* __restrict__ Sw_b,
    const float* __restrict__ Uz_b, const float* __restrict__ Wsz_b,
    const float* __restrict__ Ug_b, const float* __restrict__ Wsg_b,
    const float* __restrict__ Ur_b, const float* __restrict__ Wsr_b,
    const float* __restrict__ Uh_b, const float* __restrict__ Wsh_b,
    const float* __restrict__ Wf_w, const float* __restrict__ Wf_b,
    const int* __restrict__ n_layers_p, float* __restrict__ out) {
    extern __shared__ char smem[];
    const int tid = threadIdx.x;
    const int lane = tid & 31;
    const int warp = tid >> 5;
    const int wm = warp >> 2;   // 0..1 (m32 group)
    const int wn = warp & 3;    // 0..3 (n32 group)
    const int row0 = blockIdx.x * TM;
    const uint32_t sbase = smem_u32(smem);

    // A ldmatrix lane addresses (hi; lo at +S_TILE)
    const uint32_t aS0 =
        sbase + OFF_S + (wm * 32 + (lane & 15)) * LDT + ((lane >> 4) << 4);
    const uint32_t aS1 = aS0 + 16 * LDT;
    const uint32_t aSR0 = aS0 + (OFF_SR - OFF_S);
    const uint32_t aSR1 = aSR0 + 16 * LDT;
    // B lane offset within a W chunk (hi n-rows 0-127, lo 128-255; 80B rows)
    const uint32_t bBase = (wn * 32 + (lane & 7)) * 80 +
                           (((lane >> 3) & 1) << 4) +
                           ((lane & 16) ? 128 * 80 : 0);

    // epilogue fragment coords
    const int er = wm * 32 + (lane >> 2);
    const int ecq = (lane & 3) * 2;

    // ---- build XT tiles (hi|lo) in SR region ----
    {
        char* xh = smem + OFF_SR;
        const float4* x4 = reinterpret_cast<const float4*>(x);
        for (int idx = tid; idx < TM * 25; idx += NTHR) {
            int m = idx / 25, q = idx - m * 25;
            float4 v = x4[(size_t)(row0 + m) * 25 + q];
            float vv[4] = {v.x, v.y, v.z, v.w};
#pragma unroll
            for (int j = 0; j < 4; ++j) {
                uint32_t off = m * LDT + (q * 4 + j) * 2;
                __nv_bfloat16 h = __float2bfloat16(vv[j]);
                *(__nv_bfloat16*)(xh + off) = h;
                *(__nv_bfloat16*)(xh + S_TILE + off) =
                    __float2bfloat16(vv[j] - __bfloat162float(h));
            }
        }
        if (tid < TM) {
            float tv = t[row0 + tid];
            uint32_t off = tid * LDT + 100 * 2;
            __nv_bfloat16 h = __float2bfloat16(tv);
            *(__nv_bfloat16*)(xh + off) = h;
            *(__nv_bfloat16*)(xh + S_TILE + off) =
                __float2bfloat16(tv - __bfloat162float(h));
            for (int k = 101; k < 112; ++k) {
                uint32_t o = tid * LDT + k * 2;
                *(unsigned short*)(xh + o) = 0;
                *(unsigned short*)(xh + S_TILE + o) = 0;
            }
        }
    }
    // (gemm's internal first sync orders the XT writes)

    float acc[8][4];

    // ---- S1 = tanh(xt @ SwT + Sw_b) -> S tiles ----
    gemm_chunked<7>(sbase, 0, aSR0, aSR1, bBase, tid, acc);
#pragma unroll
    for (int nt = 0; nt < 4; ++nt)
#pragma unroll
        for (int mf = 0; mf < 2; ++mf) {
            int c = wn * 32 + nt * 8 + ecq;
            float2 b = __ldg((const float2*)(Sw_b + c));
            uint32_t o0 = (er + mf * 16) * LDT + c * 2, o1 = o0 + 8 * LDT;
            float* a = acc[nt * 2 + mf];
            store_split(smem + OFF_S, o0, fast_tanh(a[0] + b.x),
                        fast_tanh(a[1] + b.y));
            store_split(smem + OFF_S, o1, fast_tanh(a[2] + b.x),
                        fast_tanh(a[3] + b.y));
        }

    // ---- u planes (bias-folded) -> g_u ----
#pragma unroll 1
    for (int pl = 0; pl < 4; ++pl) {
        gemm_chunked<7>(sbase, pl + 1, aSR0, aSR1, bBase, tid, acc);
        const float *b1p, *b2p;
        if (pl == 0)      { b1p = Uz_b; b2p = Wsz_b; }
        else if (pl == 1) { b1p = Ug_b; b2p = Wsg_b; }
        else if (pl == 2) { b1p = Ur_b; b2p = Wsr_b; }
        else              { b1p = Uh_b; b2p = Wsh_b; }
        float* uP = g_u + ((size_t)blockIdx.x * 4 + pl) * TM * HID;
#pragma unroll
        for (int nt = 0; nt < 4; ++nt)
#pragma unroll
            for (int mf = 0; mf < 2; ++mf) {
                int r = er + mf * 16, c = wn * 32 + nt * 8 + ecq;
                float2 b1 = __ldg((const float2*)(b1p + c));
                float2 b2 = __ldg((const float2*)(b2p + c));
                float* a = acc[nt * 2 + mf];
                *(float2*)(uP + r * HID + c) =
                    make_float2(a[0] + b1.x + b2.x, a[1] + b1.y + b2.y);
                *(float2*)(uP + (r + 8) * HID + c) =
                    make_float2(a[2] + b1.x + b2.x, a[3] + b1.y + b2.y);
            }
    }

    const int nl = *n_layers_p;
    const float* uZ = g_u + ((size_t)blockIdx.x * 4 + 0) * TM * HID;
    const float* uG = g_u + ((size_t)blockIdx.x * 4 + 1) * TM * HID;
    const float* uR = g_u + ((size_t)blockIdx.x * 4 + 2) * TM * HID;
    const float* uH = g_u + ((size_t)blockIdx.x * 4 + 3) * TM * HID;

    float zs[8][4];

#pragma unroll 1
    for (int l = 1; l < nl; ++l) {
        // ---- R: SR = S * tanh(uR + S@WsrT) ----
        gemm_chunked<8>(sbase, 7, aS0, aS1, bBase, tid, acc);
#pragma unroll
        for (int nt = 0; nt < 4; ++nt)
#pragma unroll
            for (int mf = 0; mf < 2; ++mf) {
                int r = er + mf * 16, c = wn * 32 + nt * 8 + ecq;
                float2 u0 = *(const float2*)(uR + r * HID + c);
                float2 u1 = *(const float2*)(uR + (r + 8) * HID + c);
                uint32_t o0 = r * LDT + c * 2, o1 = o0 + 8 * LDT;
                float2 s0 = ld_pair(smem + OFF_S, o0);
                float2 s1 = ld_pair(smem + OFF_S, o1);
                float* a = acc[nt * 2 + mf];
                store_split(smem + OFF_SR, o0, s0.x * fast_tanh(a[0] + u0.x),
                            s0.y * fast_tanh(a[1] + u0.y));
                store_split(smem + OFF_SR, o1, s1.x * fast_tanh(a[2] + u1.x),
                            s1.y * fast_tanh(a[3] + u1.y));
            }

        // ---- Z: zs = tanh(uZ + S@WszT) * S (registers) ----
        gemm_chunked<8>(sbase, 5, aS0, aS1, bBase, tid, acc);
#pragma unroll
        for (int nt = 0; nt < 4; ++nt)
#pragma unroll
            for (int mf = 0; mf < 2; ++mf) {
                int r = er + mf * 16, c = wn * 32 + nt * 8 + ecq;
                float2 u0 = *(const float2*)(uZ + r * HID + c);
                float2 u1 = *(const float2*)(uZ + (r + 8) * HID + c);
                uint32_t o0 = r * LDT + c * 2, o1 = o0 + 8 * LDT;
                float2 s0 = ld_pair(smem + OFF_S, o0);
                float2 s1 = ld_pair(smem + OFF_S, o1);
                float* a = acc[nt * 2 + mf];
                float* z = zs[nt * 2 + mf];
                z[0] = fast_tanh(a[0] + u0.x) * s0.x;
                z[1] = fast_tanh(a[1] + u0.y) * s0.y;
                z[2] = fast_tanh(a[2] + u1.x) * s1.x;
                z[3] = fast_tanh(a[3] + u1.y) * s1.y;
            }

        // ---- G: G = tanh(uG + S@WsgT) -> parked in (now dead) S tiles ----
        gemm_chunked<8>(sbase, 6, aS0, aS1, bBase, tid, acc);
        __syncthreads();  // all warps done reading S before overwriting
#pragma unroll
        for (int nt = 0; nt < 4; ++nt)
#pragma unroll
            for (int mf = 0; mf < 2; ++mf) {
                int r = er + mf * 16, c = wn * 32 + nt * 8 + ecq;
                float2 u0 = *(const float2*)(uG + r * HID + c);
                float2 u1 = *(const float2*)(uG + (r + 8) * HID + c);
                uint32_t o0 = r * LDT + c * 2, o1 = o0 + 8 * LDT;
                float* a = acc[nt * 2 + mf];
                store_split(smem + OFF_S, o0, fast_tanh(a[0] + u0.x),
                            fast_tanh(a[1] + u0.y));
                store_split(smem + OFF_S, o1, fast_tanh(a[2] + u1.x),
                            fast_tanh(a[3] + u1.y));
            }

        // ---- H: S_new = (1-G)*(uH + SR@WshT) + zs -> S tiles (own cells) ----
        gemm_chunked<8>(sbase, 8, aSR0, aSR1, bBase, tid, acc);
#pragma unroll
        for (int nt = 0; nt < 4; ++nt)
#pragma unroll
            for (int mf = 0; mf < 2; ++mf) {
                int r = er + mf * 16, c = wn * 32 + nt * 8 + ecq;
                float2 u0 = *(const float2*)(uH + r * HID + c);
                float2 u1 = *(const float2*)(uH + (r + 8) * HID + c);
                uint32_t o0 = r * LDT + c * 2, o1 = o0 + 8 * LDT;
                float2 g0 = ld_pair(smem + OFF_S, o0);
                float2 g1 = ld_pair(smem + OFF_S, o1);
                float* a = acc[nt * 2 + mf];
                float* z = zs[nt * 2 + mf];
                store_split(smem + OFF_S, o0,
                            (1.0f - g0.x) * (a[0] + u0.x) + z[0],
                            (1.0f - g0.y) * (a[1] + u0.y) + z[1]);
                store_split(smem + OFF_S, o1,
                            (1.0f - g1.x) * (a[2] + u1.x) + z[2],
                            (1.0f - g1.y) * (a[3] + u1.y) + z[3]);
            }
        // next gemm's internal first sync orders these writes
    }

    // ---- final: out = S @ Wf + bf (4 threads per row, shfl reduce) ----
    __syncthreads();
    {
        const int orow = tid >> 2, q = tid & 3;
        float s = 0.0f;
#pragma unroll 4
        for (int cc = 0; cc < 16; ++cc) {
            int col = q * 32 + cc * 2;
            float2 sv = ld_pair(smem + OFF_S, orow * LDT + col * 2);
            float2 wf = __ldg((const float2*)(Wf_w + col));
            s += sv.x * wf.x + sv.y * wf.y;
        }
        s += __shfl_xor_sync(0xFFFFFFFFu, s, 1);
        s += __shfl_xor_sync(0xFFFFFFFFu, s, 2);
        if (q == 0) out[row0 + orow] = s + Wf_b[0];
    }
}

extern "C" void kernel_launch(void* const* d_in, const int* in_sizes, int n_in,
                              void* d_out, int out_size) {
    const float* x     = (const float*)d_in[0];
    const float* t     = (const float*)d_in[1];
    const float* Sw_w  = (const float*)d_in[2];
    const float* Sw_b  = (const float*)d_in[3];
    const float* Uz_w  = (const float*)d_in[4];
    const float* Uz_b  = (const float*)d_in[5];
    const float* Wsz_w = (const float*)d_in[6];
    const float* Wsz_b = (const float*)d_in[7];
    const float* Ug_w  = (const float*)d_in[8];
    const float* Ug_b  = (const float*)d_in[9];
    const float* Wsg_w = (const float*)d_in[10];
    const float* Wsg_b = (const float*)d_in[11];
    const float* Ur_w  = (const float*)d_in[12];
    const float* Ur_b  = (const float*)d_in[13];
    const float* Wsr_w = (const float*)d_in[14];
    const float* Wsr_b = (const float*)d_in[15];
    const float* Uh_w  = (const float*)d_in[16];
    const float* Uh_b  = (const float*)d_in[17];
    const float* Wsh_w = (const float*)d_in[18];
    const float* Wsh_b = (const float*)d_in[19];
    const float* Wf_w  = (const float*)d_in[20];
    const float* Wf_b  = (const float*)d_in[21];
    const int*   nlp   = (const int*)d_in[22];
    float* out = (float*)d_out;

    static bool attr_set = false;
    if (!attr_set) {
        cudaFuncSetAttribute(dgm_mma_kernel,
                             cudaFuncAttributeMaxDynamicSharedMemorySize,
                             SMEM_TOTAL);
        attr_set = true;
    }
    prep_weights<<<9, 256>>>(Sw_w, Uz_w, Ug_w, Ur_w, Uh_w,
                             Wsz_w, Wsg_w, Wsr_w, Wsh_w);
    dgm_mma_kernel<<<NBLK, NTHR, SMEM_TOTAL>>>(
        x, t, Sw_b, Uz_b, Wsz_b, Ug_b, Wsg_b, Ur_b, Wsr_b, Uh_b, Wsh_b,
        Wf_w, Wf_b, nlp, out);
}

// round 16
// speedup vs baseline: 1.0939x; 1.0541x over previous
#include <cuda_runtime.h>
#include <cuda_bf16.h>
#include <cstdint>

// R16: HMMA bf16 hi/lo-split DGM = R15 (m32n32 x 8 warps, chunked W,
// 2 CTAs/SM) + gate-level software pipelining: chunk-0 cp.async of gate N+1
// is issued BEFORE gate N's epilogue, so the epilogue hides the copy latency
// that R15 paid serially 17x per pass.

namespace {
constexpr int XD   = 100;
constexpr int HID  = 128;
constexpr int TM   = 64;
constexpr int NTHR = 256;           // 8 warps: wm=warp>>2 (m32), wn=warp&3 (n32)
constexpr int NBLK = 4096;          // 262144 / TM

constexpr int LDT    = 272;         // S/SR tile row stride (136 bf16)
constexpr int S_TILE = 64 * LDT;    // 17408
constexpr int OFF_S  = 0;           // S hi | lo (34816)
constexpr int OFF_SR = 2 * S_TILE;  // SR / XT hi | lo (34816)
constexpr int OFF_W  = 4 * S_TILE;  // 69632: 2 chunk buffers
constexpr int W_CHUNK = 256 * 80;   // 20480: [hi 128 n-rows | lo 128] x 80B
constexpr int SMEM_TOTAL = OFF_W + 2 * W_CHUNK;  // 110592 (2 CTAs/SM)
}

// weight images: [mat][hi|lo][n][k 0..135] bf16 row-major.
// 0 Sw, 1 Uz, 2 Ug, 3 Ur, 4 Uh, 5 Wsz, 6 Wsg, 7 Wsr, 8 Wsh
__device__ __align__(16) unsigned short g_w[9][2][128][136];
// u planes (z,g,r,h), bias-folded fp32: [blk][plane][row][col]
__device__ float g_u[(size_t)NBLK * 4 * TM * HID];

__device__ __forceinline__ uint32_t smem_u32(const void* p) {
    uint32_t a;
    asm("{ .reg .u64 t; cvta.to.shared.u64 t, %1; cvt.u32.u64 %0, t; }"
        : "=r"(a) : "l"(p));
    return a;
}
__device__ __forceinline__ float bf2f(uint32_t u) {
    return __bfloat162float(__ushort_as_bfloat16((unsigned short)u));
}
__device__ __forceinline__ uint32_t f2bf2(float lo, float hi) {
    uint32_t r;
    asm("cvt.rn.bf16x2.f32 %0, %1, %2;" : "=r"(r) : "f"(hi), "f"(lo));
    return r;
}
__device__ __forceinline__ void store_split(char* base, uint32_t off,
                                            float v0, float v1) {
    uint32_t hp = f2bf2(v0, v1);
    *(uint32_t*)(base + off) = hp;
    *(uint32_t*)(base + S_TILE + off) =
        f2bf2(v0 - bf2f(hp & 0xffffu), v1 - bf2f(hp >> 16));
}
__device__ __forceinline__ float2 ld_pair(const char* base, uint32_t off) {
    uint32_t h = *(const uint32_t*)(base + off);
    uint32_t l = *(const uint32_t*)(base + S_TILE + off);
    return make_float2(bf2f(h & 0xffffu) + bf2f(l & 0xffffu),
                       bf2f(h >> 16) + bf2f(l >> 16));
}
__device__ __forceinline__ float fast_tanh(float v) {
    float e = __expf(2.0f * v);
    return 1.0f - __fdividef(2.0f, e + 1.0f);
}
__device__ __forceinline__ void ldsm4(uint32_t* r, uint32_t a) {
    asm volatile("ldmatrix.sync.aligned.m8n8.x4.shared.b16 {%0,%1,%2,%3}, [%4];"
                 : "=r"(r[0]), "=r"(r[1]), "=r"(r[2]), "=r"(r[3]) : "r"(a));
}
__device__ __forceinline__ void mma16816(float* d, const uint32_t* a,
                                         const uint32_t* b) {
    asm volatile(
        "mma.sync.aligned.m16n8k16.row.col.f32.bf16.bf16.f32 "
        "{%0,%1,%2,%3}, {%4,%5,%6,%7}, {%8,%9}, {%0,%1,%2,%3};"
        : "+f"(d[0]), "+f"(d[1]), "+f"(d[2]), "+f"(d[3])
        : "r"(a[0]), "r"(a[1]), "r"(a[2]), "r"(a[3]), "r"(b[0]), "r"(b[1]));
}

__global__ void prep_weights(const float* Sw, const float* Uz, const float* Ug,
                             const float* Ur, const float* Uh, const float* Wsz,
                             const float* Wsg, const float* Wsr, const float* Wsh) {
    int m = blockIdx.x;
    const float* src;
    int Ks;
    switch (m) {
        case 0: src = Sw;  Ks = 101; break;
        case 1: src = Uz;  Ks = 101; break;
        case 2: src = Ug;  Ks = 101; break;
        case 3: src = Ur;  Ks = 101; break;
        case 4: src = Uh;  Ks = 101; break;
        case 5: src = Wsz; Ks = 128; break;
        case 6: src = Wsg; Ks = 128; break;
        case 7: src = Wsr; Ks = 128; break;
        default: src = Wsh; Ks = 128; break;
    }
    for (int idx = threadIdx.x; idx < 128 * 136; idx += blockDim.x) {
        int n = idx / 136, k = idx - n * 136;
        float v = (k < Ks) ? src[(size_t)k * HID + n] : 0.0f;  // Bt[n][k]
        __nv_bfloat16 h = __float2bfloat16(v);
        g_w[m][0][n][k] = __bfloat16_as_ushort(h);
        g_w[m][1][n][k] =
            __bfloat16_as_ushort(__float2bfloat16(v - __bfloat162float(h)));
    }
}

// copy k-slice [k0, k0+kc) (kc = 32 or 16) of gate `mat` into chunk buffer
// at sb; smem row stride 80B (hi n-rows 0-127, lo 128-255).
__device__ __forceinline__ void cp_chunkW(uint32_t sb, int mat, int k0, int kc,
                                          int tid) {
    const char* src = (const char*)g_w[mat];
    if (kc == 32) {
#pragma unroll
        for (int u = tid; u < 1024; u += NTHR) {
            int row = u >> 2, seg = u & 3;
            asm volatile("cp.async.cg.shared.global [%0], [%1], 16;"
                         :: "r"(sb + row * 80 + seg * 16),
                            "l"(src + (size_t)row * 272 + k0 * 2 + seg * 16)
                         : "memory");
        }
    } else {
#pragma unroll
        for (int u = tid; u < 512; u += NTHR) {
            int row = u >> 1, seg = u & 1;
            asm volatile("cp.async.cg.shared.global [%0], [%1], 16;"
                         :: "r"(sb + row * 80 + seg * 16),
                            "l"(src + (size_t)row * 272 + k0 * 2 + seg * 16)
                         : "memory");
        }
    }
    asm volatile("cp.async.commit_group;" ::: "memory");
}

// Issue chunk 0 of gate `mat` into W buffer 0 (gate-level pipelining).
__device__ __forceinline__ void gemm_start(uint32_t sbase, int mat, int tid) {
    cp_chunkW(sbase + OFF_W, mat, 0, 32, tid);
}

// acc[nt*2+mf][4]: warp tile m32 x n32 over K = KK*16. Chunk 0 must already
// be in flight (gemm_start). Prefetches chunks 1..CH-1 internally.
// Contains __syncthreads -> call uniformly.
template <int KK>
__device__ __forceinline__ void gemm_run(uint32_t sbase, int mat,
                                         uint32_t aHi0, uint32_t aHi1,
                                         uint32_t bBase, int tid,
                                         float acc[8][4]) {
    constexpr int K = KK * 16;
    constexpr int CH = (K + 31) / 32;
#pragma unroll
    for (int i = 0; i < 8; ++i) {
        acc[i][0] = 0.f; acc[i][1] = 0.f; acc[i][2] = 0.f; acc[i][3] = 0.f;
    }
#pragma unroll
    for (int ch = 0; ch < CH; ++ch) {
        asm volatile("cp.async.wait_group 0;" ::: "memory");
        __syncthreads();
        if (ch + 1 < CH) {
            const int nk0 = (ch + 1) * 32;
            cp_chunkW(sbase + OFF_W + ((ch + 1) & 1) * W_CHUNK, mat, nk0,
                      (K - nk0 < 32 ? K - nk0 : 32), tid);
        }
        const uint32_t wb = sbase + OFF_W + (ch & 1) * W_CHUNK + bBase;
        const int kkc = (KK - ch * 2 < 2) ? (KK - ch * 2) : 2;
#pragma unroll
        for (int kkl = 0; kkl < 2; ++kkl) {
            if (kkl >= kkc) break;
            const uint32_t ka = (ch * 32 + kkl * 16) * 2;
            uint32_t ah0[4], al0[4], ah1[4], al1[4];
            ldsm4(ah0, aHi0 + ka);
            ldsm4(al0, aHi0 + ka + S_TILE);
            ldsm4(ah1, aHi1 + ka);
            ldsm4(al1, aHi1 + ka + S_TILE);
#pragma unroll
            for (int nt = 0; nt < 4; ++nt) {
                uint32_t b[4];
                ldsm4(b, wb + nt * 640 + kkl * 32);
                mma16816(acc[nt * 2 + 0], ah0, b);
                mma16816(acc[nt * 2 + 0], ah0, b + 2);
                mma16816(acc[nt * 2 + 0], al0, b);
                mma16816(acc[nt * 2 + 1], ah1, b);
                mma16816(acc[nt * 2 + 1], ah1, b + 2);
                mma16816(acc[nt * 2 + 1], al1, b);
            }
        }
    }
    // note: no trailing sync; chunk-0 pre-issue into buffer 0 is WAR-safe
    // (buffer 0 last read at chunk CH-2, fenced by the top-of-chunk sync).
}

__global__ void __launch_bounds__(NTHR, 2) dgm_mma_kernel(
    const float* __restrict__ x, const float* __restrict__ t,
    const float* __restrict__ Sw_b,
    const float* __restrict__ Uz_b, const float* __restrict__ Wsz_b,
    const float* __restrict__ Ug_b, const float* __restrict__ Wsg_b,
    const float* __restrict__ Ur_b, const float* __restrict__ Wsr_b,
    const float* __restrict__ Uh_b, const float* __restrict__ Wsh_b,
    const float* __restrict__ Wf_w, const float* __restrict__ Wf_b,
    const int* __restrict__ n_layers_p, float* __restrict__ out) {
    extern __shared__ char smem[];
    const int tid = threadIdx.x;
    const int lane = tid & 31;
    const int warp = tid >> 5;
    const int wm = warp >> 2;   // 0..1 (m32 group)
    const int wn = warp & 3;    // 0..3 (n32 group)
    const int row0 = blockIdx.x * TM;
    const uint32_t sbase = smem_u32(smem);

    // A ldmatrix lane addresses (hi; lo at +S_TILE)
    const uint32_t aS0 =
        sbase + OFF_S + (wm * 32 + (lane & 15)) * LDT + ((lane >> 4) << 4);
    const uint32_t aS1 = aS0 + 16 * LDT;
    const uint32_t aSR0 = aS0 + (OFF_SR - OFF_S);
    const uint32_t aSR1 = aSR0 + 16 * LDT;
    // B lane offset within a W chunk (hi n-rows 0-127, lo 128-255; 80B rows)
    const uint32_t bBase = (wn * 32 + (lane & 7)) * 80 +
                           (((lane >> 3) & 1) << 4) +
                           ((lane & 16) ? 128 * 80 : 0);

    // epilogue fragment coords
    const int er = wm * 32 + (lane >> 2);
    const int ecq = (lane & 3) * 2;

    // chunk-0 of Sw in flight while we stage XT
    gemm_start(sbase, 0, tid);

    // ---- build XT tiles (hi|lo) in SR region ----
    {
        char* xh = smem + OFF_SR;
        const float4* x4 = reinterpret_cast<const float4*>(x);
        for (int idx = tid; idx < TM * 25; idx += NTHR) {
            int m = idx / 25, q = idx - m * 25;
            float4 v = x4[(size_t)(row0 + m) * 25 + q];
            float vv[4] = {v.x, v.y, v.z, v.w};
#pragma unroll
            for (int j = 0; j < 4; ++j) {
                uint32_t off = m * LDT + (q * 4 + j) * 2;
                __nv_bfloat16 h = __float2bfloat16(vv[j]);
                *(__nv_bfloat16*)(xh + off) = h;
                *(__nv_bfloat16*)(xh + S_TILE + off) =
                    __float2bfloat16(vv[j] - __bfloat162float(h));
            }
        }
        if (tid < TM) {
            float tv = t[row0 + tid];
            uint32_t off = tid * LDT + 100 * 2;
            __nv_bfloat16 h = __float2bfloat16(tv);
            *(__nv_bfloat16*)(xh + off) = h;
            *(__nv_bfloat16*)(xh + S_TILE + off) =
                __float2bfloat16(tv - __bfloat162float(h));
            for (int k = 101; k < 112; ++k) {
                uint32_t o = tid * LDT + k * 2;
                *(unsigned short*)(xh + o) = 0;
                *(unsigned short*)(xh + S_TILE + o) = 0;
            }
        }
    }
    // (gemm_run's internal first sync orders the XT writes)

    float acc[8][4];

    // ---- S1 = tanh(xt @ SwT + Sw_b) -> S tiles ----
    gemm_run<7>(sbase, 0, aSR0, aSR1, bBase, tid, acc);
    gemm_start(sbase, 1, tid);  // Uz chunk0 overlaps S1 epilogue
#pragma unroll
    for (int nt = 0; nt < 4; ++nt)
#pragma unroll
        for (int mf = 0; mf < 2; ++mf) {
            int c = wn * 32 + nt * 8 + ecq;
            float2 b = __ldg((const float2*)(Sw_b + c));
            uint32_t o0 = (er + mf * 16) * LDT + c * 2, o1 = o0 + 8 * LDT;
            float* a = acc[nt * 2 + mf];
            store_split(smem + OFF_S, o0, fast_tanh(a[0] + b.x),
                        fast_tanh(a[1] + b.y));
            store_split(smem + OFF_S, o1, fast_tanh(a[2] + b.x),
                        fast_tanh(a[3] + b.y));
        }

    // ---- u planes (bias-folded) -> g_u ----
#pragma unroll 1
    for (int pl = 0; pl < 4; ++pl) {
        gemm_run<7>(sbase, pl + 1, aSR0, aSR1, bBase, tid, acc);
        gemm_start(sbase, pl < 3 ? pl + 2 : 7, tid);  // next U / first Wsr
        const float *b1p, *b2p;
        if (pl == 0)      { b1p = Uz_b; b2p = Wsz_b; }
        else if (pl == 1) { b1p = Ug_b; b2p = Wsg_b; }
        else if (pl == 2) { b1p = Ur_b; b2p = Wsr_b; }
        else              { b1p = Uh_b; b2p = Wsh_b; }
        float* uP = g_u + ((size_t)blockIdx.x * 4 + pl) * TM * HID;
#pragma unroll
        for (int nt = 0; nt < 4; ++nt)
#pragma unroll
            for (int mf = 0; mf < 2; ++mf) {
                int r = er + mf * 16, c = wn * 32 + nt * 8 + ecq;
                float2 b1 = __ldg((const float2*)(b1p + c));
                float2 b2 = __ldg((const float2*)(b2p + c));
                float* a = acc[nt * 2 + mf];
                *(float2*)(uP + r * HID + c) =
                    make_float2(a[0] + b1.x + b2.x, a[1] + b1.y + b2.y);
                *(float2*)(uP + (r + 8) * HID + c) =
                    make_float2(a[2] + b1.x + b2.x, a[3] + b1.y + b2.y);
            }
    }

    const int nl = *n_layers_p;
    const float* uZ = g_u + ((size_t)blockIdx.x * 4 + 0) * TM * HID;
    const float* uG = g_u + ((size_t)blockIdx.x * 4 + 1) * TM * HID;
    const float* uR = g_u + ((size_t)blockIdx.x * 4 + 2) * TM * HID;
    const float* uH = g_u + ((size_t)blockIdx.x * 4 + 3) * TM * HID;

    float zs[8][4];

#pragma unroll 1
    for (int l = 1; l < nl; ++l) {
        // ---- R: SR = S * tanh(uR + S@WsrT) ----
        gemm_run<8>(sbase, 7, aS0, aS1, bBase, tid, acc);
        gemm_start(sbase, 5, tid);  // Wsz chunk0 overlaps R epilogue
#pragma unroll
        for (int nt = 0; nt < 4; ++nt)
#pragma unroll
            for (int mf = 0; mf < 2; ++mf) {
                int r = er + mf * 16, c = wn * 32 + nt * 8 + ecq;
                float2 u0 = *(const float2*)(uR + r * HID + c);
                float2 u1 = *(const float2*)(uR + (r + 8) * HID + c);
                uint32_t o0 = r * LDT + c * 2, o1 = o0 + 8 * LDT;
                float2 s0 = ld_pair(smem + OFF_S, o0);
                float2 s1 = ld_pair(smem + OFF_S, o1);
                float* a = acc[nt * 2 + mf];
                store_split(smem + OFF_SR, o0, s0.x * fast_tanh(a[0] + u0.x),
                            s0.y * fast_tanh(a[1] + u0.y));
                store_split(smem + OFF_SR, o1, s1.x * fast_tanh(a[2] + u1.x),
                            s1.y * fast_tanh(a[3] + u1.y));
            }

        // ---- Z: zs = tanh(uZ + S@WszT) * S (registers) ----
        gemm_run<8>(sbase, 5, aS0, aS1, bBase, tid, acc);
        gemm_start(sbase, 6, tid);  // Wsg
#pragma unroll
        for (int nt = 0; nt < 4; ++nt)
#pragma unroll
            for (int mf = 0; mf < 2; ++mf) {
                int r = er + mf * 16, c = wn * 32 + nt * 8 + ecq;
                float2 u0 = *(const float2*)(uZ + r * HID + c);
                float2 u1 = *(const float2*)(uZ + (r + 8) * HID + c);
                uint32_t o0 = r * LDT + c * 2, o1 = o0 + 8 * LDT;
                float2 s0 = ld_pair(smem + OFF_S, o0);
                float2 s1 = ld_pair(smem + OFF_S, o1);
                float* a = acc[nt * 2 + mf];
                float* z = zs[nt * 2 + mf];
                z[0] = fast_tanh(a[0] + u0.x) * s0.x;
                z[1] = fast_tanh(a[1] + u0.y) * s0.y;
                z[2] = fast_tanh(a[2] + u1.x) * s1.x;
                z[3] = fast_tanh(a[3] + u1.y) * s1.y;
            }

        // ---- G: G = tanh(uG + S@WsgT) -> parked in (now dead) S tiles ----
        gemm_run<8>(sbase, 6, aS0, aS1, bBase, tid, acc);
        gemm_start(sbase, 8, tid);  // Wsh
        __syncthreads();  // all warps done reading S before overwriting
#pragma unroll
        for (int nt = 0; nt < 4; ++nt)
#pragma unroll
            for (int mf = 0; mf < 2; ++mf) {
                int r = er + mf * 16, c = wn * 32 + nt * 8 + ecq;
                float2 u0 = *(const float2*)(uG + r * HID + c);
                float2 u1 = *(const float2*)(uG + (r + 8) * HID + c);
                uint32_t o0 = r * LDT + c * 2, o1 = o0 + 8 * LDT;
                float* a = acc[nt * 2 + mf];
                store_split(smem + OFF_S, o0, fast_tanh(a[0] + u0.x),
                            fast_tanh(a[1] + u0.y));
                store_split(smem + OFF_S, o1, fast_tanh(a[2] + u1.x),
                            fast_tanh(a[3] + u1.y));
            }

        // ---- H: S_new = (1-G)*(uH + SR@WshT) + zs -> S tiles (own cells) ----
        gemm_run<8>(sbase, 8, aSR0, aSR1, bBase, tid, acc);
        if (l + 1 < nl) gemm_start(sbase, 7, tid);  // next layer's Wsr
#pragma unroll
        for (int nt = 0; nt < 4; ++nt)
#pragma unroll
            for (int mf = 0; mf < 2; ++mf) {
                int r = er + mf * 16, c = wn * 32 + nt * 8 + ecq;
                float2 u0 = *(const float2*)(uH + r * HID + c);
                float2 u1 = *(const float2*)(uH + (r + 8) * HID + c);
                uint32_t o0 = r * LDT + c * 2, o1 = o0 + 8 * LDT;
                float2 g0 = ld_pair(smem + OFF_S, o0);
                float2 g1 = ld_pair(smem + OFF_S, o1);
                float* a = acc[nt * 2 + mf];
                float* z = zs[nt * 2 + mf];
                store_split(smem + OFF_S, o0,
                            (1.0f - g0.x) * (a[0] + u0.x) + z[0],
                            (1.0f - g0.y) * (a[1] + u0.y) + z[1]);
                store_split(smem + OFF_S, o1,
                            (1.0f - g1.x) * (a[2] + u1.x) + z[2],
                            (1.0f - g1.y) * (a[3] + u1.y) + z[3]);
            }
        // next gemm_run's internal first sync orders these writes
    }

    // ---- final: out = S @ Wf + bf (4 threads per row, shfl reduce) ----
    __syncthreads();
    {
        const int orow = tid >> 2, q = tid & 3;
        float s = 0.0f;
#pragma unroll 4
        for (int cc = 0; cc < 16; ++cc) {
            int col = q * 32 + cc * 2;
            float2 sv = ld_pair(smem + OFF_S, orow * LDT + col * 2);
            float2 wf = __ldg((const float2*)(Wf_w + col));
            s += sv.x * wf.x + sv.y * wf.y;
        }
        s += __shfl_xor_sync(0xFFFFFFFFu, s, 1);
        s += __shfl_xor_sync(0xFFFFFFFFu, s, 2);
        if (q == 0) out[row0 + orow] = s + Wf_b[0];
    }
}

extern "C" void kernel_launch(void* const* d_in, const int* in_sizes, int n_in,
                              void* d_out, int out_size) {
    const float* x     = (const float*)d_in[0];
    const float* t     = (const float*)d_in[1];
    const float* Sw_w  = (const float*)d_in[2];
    const float* Sw_b  = (const float*)d_in[3];
    const float* Uz_w  = (const float*)d_in[4];
    const float* Uz_b  = (const float*)d_in[5];
    const float* Wsz_w = (const float*)d_in[6];
    const float* Wsz_b = (const float*)d_in[7];
    const float* Ug_w  = (const float*)d_in[8];
    const float* Ug_b  = (const float*)d_in[9];
    const float* Wsg_w = (const float*)d_in[10];
    const float* Wsg_b = (const float*)d_in[11];
    const float* Ur_w  = (const float*)d_in[12];
    const float* Ur_b  = (const float*)d_in[13];
    const float* Wsr_w = (const float*)d_in[14];
    const float* Wsr_b = (const float*)d_in[15];
    const float* Uh_w  = (const float*)d_in[16];
    const float* Uh_b  = (const float*)d_in[17];
    const float* Wsh_w = (const float*)d_in[18];
    const float* Wsh_b = (const float*)d_in[19];
    const float* Wf_w  = (const float*)d_in[20];
    const float* Wf_b  = (const float*)d_in[21];
    const int*   nlp   = (const int*)d_in[22];
    float* out = (float*)d_out;

    static bool attr_set = false;
    if (!attr_set) {
        cudaFuncSetAttribute(dgm_mma_kernel,
                             cudaFuncAttributeMaxDynamicSharedMemorySize,
                             SMEM_TOTAL);
        attr_set = true;
    }
    prep_weights<<<9, 256>>>(Sw_w, Uz_w, Ug_w, Ur_w, Uh_w,
                             Wsz_w, Wsg_w, Wsr_w, Wsh_w);
    dgm_mma_kernel<<<NBLK, NTHR, SMEM_TOTAL>>>(
        x, t, Sw_b, Uz_b, Wsz_b, Ug_b, Wsg_b, Ur_b, Wsr_b, Uh_b, Wsh_b,
        Wf_w, Wf_b, nlp, out);
}

// round 17
// speedup vs baseline: 1.0989x; 1.0045x over previous
#include <cuda_runtime.h>
#include <cuda_bf16.h>
#include <cstdint>

// R17: HMMA bf16 hi/lo-split DGM = R16 + TM doubled to 128 rows/CTA
// (512 threads, 16 warps, m32n32 warp tiles, 1 CTA/SM).
// Rationale (R16 ncu): L2=44% was gate-weight re-streaming (17 x 70KB per
// CTA x 4096 CTAs ~ 4.9GB ~ 500us at LTS cap). Halving CTA count at equal
// rows halves W L2 traffic and halves chunk-barrier overhead per MAC, with
// identical per-warp tile shape / register budget (128) as R16.

namespace {
constexpr int XD   = 100;
constexpr int HID  = 128;
constexpr int TM   = 128;
constexpr int NTHR = 512;           // 16 warps: wm=warp>>2 (m32), wn=warp&3
constexpr int NBLK = 2048;          // 262144 / TM

constexpr int LDT    = 272;         // S/SR tile row stride (136 bf16)
constexpr int S_TILE = TM * LDT;    // 34816
constexpr int OFF_S  = 0;           // S hi | lo (69632)
constexpr int OFF_SR = 2 * S_TILE;  // SR / XT hi | lo (69632)
constexpr int OFF_W  = 4 * S_TILE;  // 139264: 2 chunk buffers
constexpr int W_CHUNK = 256 * 80;   // 20480: [hi 128 n-rows | lo 128] x 80B
constexpr int SMEM_TOTAL = OFF_W + 2 * W_CHUNK;  // 180224 (1 CTA/SM)
}

// weight images: [mat][hi|lo][n][k 0..135] bf16 row-major.
// 0 Sw, 1 Uz, 2 Ug, 3 Ur, 4 Uh, 5 Wsz, 6 Wsg, 7 Wsr, 8 Wsh
__device__ __align__(16) unsigned short g_w[9][2][128][136];
// u planes (z,g,r,h), bias-folded fp32: [blk][plane][row][col]
__device__ float g_u[(size_t)NBLK * 4 * TM * HID];

__device__ __forceinline__ uint32_t smem_u32(const void* p) {
    uint32_t a;
    asm("{ .reg .u64 t; cvta.to.shared.u64 t, %1; cvt.u32.u64 %0, t; }"
        : "=r"(a) : "l"(p));
    return a;
}
__device__ __forceinline__ float bf2f(uint32_t u) {
    return __bfloat162float(__ushort_as_bfloat16((unsigned short)u));
}
__device__ __forceinline__ uint32_t f2bf2(float lo, float hi) {
    uint32_t r;
    asm("cvt.rn.bf16x2.f32 %0, %1, %2;" : "=r"(r) : "f"(hi), "f"(lo));
    return r;
}
__device__ __forceinline__ void store_split(char* base, uint32_t off,
                                            float v0, float v1) {
    uint32_t hp = f2bf2(v0, v1);
    *(uint32_t*)(base + off) = hp;
    *(uint32_t*)(base + S_TILE + off) =
        f2bf2(v0 - bf2f(hp & 0xffffu), v1 - bf2f(hp >> 16));
}
__device__ __forceinline__ float2 ld_pair(const char* base, uint32_t off) {
    uint32_t h = *(const uint32_t*)(base + off);
    uint32_t l = *(const uint32_t*)(base + S_TILE + off);
    return make_float2(bf2f(h & 0xffffu) + bf2f(l & 0xffffu),
                       bf2f(h >> 16) + bf2f(l >> 16));
}
__device__ __forceinline__ float fast_tanh(float v) {
    float e = __expf(2.0f * v);
    return 1.0f - __fdividef(2.0f, e + 1.0f);
}
__device__ __forceinline__ void ldsm4(uint32_t* r, uint32_t a) {
    asm volatile("ldmatrix.sync.aligned.m8n8.x4.shared.b16 {%0,%1,%2,%3}, [%4];"
                 : "=r"(r[0]), "=r"(r[1]), "=r"(r[2]), "=r"(r[3]) : "r"(a));
}
__device__ __forceinline__ void mma16816(float* d, const uint32_t* a,
                                         const uint32_t* b) {
    asm volatile(
        "mma.sync.aligned.m16n8k16.row.col.f32.bf16.bf16.f32 "
        "{%0,%1,%2,%3}, {%4,%5,%6,%7}, {%8,%9}, {%0,%1,%2,%3};"
        : "+f"(d[0]), "+f"(d[1]), "+f"(d[2]), "+f"(d[3])
        : "r"(a[0]), "r"(a[1]), "r"(a[2]), "r"(a[3]), "r"(b[0]), "r"(b[1]));
}

__global__ void prep_weights(const float* Sw, const float* Uz, const float* Ug,
                             const float* Ur, const float* Uh, const float* Wsz,
                             const float* Wsg, const float* Wsr, const float* Wsh) {
    int m = blockIdx.x;
    const float* src;
    int Ks;
    switch (m) {
        case 0: src = Sw;  Ks = 101; break;
        case 1: src = Uz;  Ks = 101; break;
        case 2: src = Ug;  Ks = 101; break;
        case 3: src = Ur;  Ks = 101; break;
        case 4: src = Uh;  Ks = 101; break;
        case 5: src = Wsz; Ks = 128; break;
        case 6: src = Wsg; Ks = 128; break;
        case 7: src = Wsr; Ks = 128; break;
        default: src = Wsh; Ks = 128; break;
    }
    for (int idx = threadIdx.x; idx < 128 * 136; idx += blockDim.x) {
        int n = idx / 136, k = idx - n * 136;
        float v = (k < Ks) ? src[(size_t)k * HID + n] : 0.0f;  // Bt[n][k]
        __nv_bfloat16 h = __float2bfloat16(v);
        g_w[m][0][n][k] = __bfloat16_as_ushort(h);
        g_w[m][1][n][k] =
            __bfloat16_as_ushort(__float2bfloat16(v - __bfloat162float(h)));
    }
}

// copy k-slice [k0, k0+kc) (kc = 32 or 16) of gate `mat` into chunk buffer
// at sb; smem row stride 80B (hi n-rows 0-127, lo 128-255).
__device__ __forceinline__ void cp_chunkW(uint32_t sb, int mat, int k0, int kc,
                                          int tid) {
    const char* src = (const char*)g_w[mat];
    if (kc == 32) {
#pragma unroll
        for (int u = tid; u < 1024; u += NTHR) {
            int row = u >> 2, seg = u & 3;
            asm volatile("cp.async.cg.shared.global [%0], [%1], 16;"
                         :: "r"(sb + row * 80 + seg * 16),
                            "l"(src + (size_t)row * 272 + k0 * 2 + seg * 16)
                         : "memory");
        }
    } else {
#pragma unroll
        for (int u = tid; u < 512; u += NTHR) {
            int row = u >> 1, seg = u & 1;
            asm volatile("cp.async.cg.shared.global [%0], [%1], 16;"
                         :: "r"(sb + row * 80 + seg * 16),
                            "l"(src + (size_t)row * 272 + k0 * 2 + seg * 16)
                         : "memory");
        }
    }
    asm volatile("cp.async.commit_group;" ::: "memory");
}

// Issue chunk 0 of gate `mat` into W buffer 0 (gate-level pipelining).
__device__ __forceinline__ void gemm_start(uint32_t sbase, int mat, int tid) {
    cp_chunkW(sbase + OFF_W, mat, 0, 32, tid);
}

// acc[nt*2+mf][4]: warp tile m32 x n32 over K = KK*16. Chunk 0 must already
// be in flight (gemm_start). Prefetches chunks 1..CH-1 internally.
// Contains __syncthreads -> call uniformly.
template <int KK>
__device__ __forceinline__ void gemm_run(uint32_t sbase, int mat,
                                         uint32_t aHi0, uint32_t aHi1,
                                         uint32_t bBase, int tid,
                                         float acc[8][4]) {
    constexpr int K = KK * 16;
    constexpr int CH = (K + 31) / 32;
#pragma unroll
    for (int i = 0; i < 8; ++i) {
        acc[i][0] = 0.f; acc[i][1] = 0.f; acc[i][2] = 0.f; acc[i][3] = 0.f;
    }
#pragma unroll
    for (int ch = 0; ch < CH; ++ch) {
        asm volatile("cp.async.wait_group 0;" ::: "memory");
        __syncthreads();
        if (ch + 1 < CH) {
            const int nk0 = (ch + 1) * 32;
            cp_chunkW(sbase + OFF_W + ((ch + 1) & 1) * W_CHUNK, mat, nk0,
                      (K - nk0 < 32 ? K - nk0 : 32), tid);
        }
        const uint32_t wb = sbase + OFF_W + (ch & 1) * W_CHUNK + bBase;
        const int kkc = (KK - ch * 2 < 2) ? (KK - ch * 2) : 2;
#pragma unroll
        for (int kkl = 0; kkl < 2; ++kkl) {
            if (kkl >= kkc) break;
            const uint32_t ka = (ch * 32 + kkl * 16) * 2;
            uint32_t ah0[4], al0[4], ah1[4], al1[4];
            ldsm4(ah0, aHi0 + ka);
            ldsm4(al0, aHi0 + ka + S_TILE);
            ldsm4(ah1, aHi1 + ka);
            ldsm4(al1, aHi1 + ka + S_TILE);
#pragma unroll
            for (int nt = 0; nt < 4; ++nt) {
                uint32_t b[4];
                ldsm4(b, wb + nt * 640 + kkl * 32);
                mma16816(acc[nt * 2 + 0], ah0, b);
                mma16816(acc[nt * 2 + 0], ah0, b + 2);
                mma16816(acc[nt * 2 + 0], al0, b);
                mma16816(acc[nt * 2 + 1], ah1, b);
                mma16816(acc[nt * 2 + 1], ah1, b + 2);
                mma16816(acc[nt * 2 + 1], al1, b);
            }
        }
    }
    // no trailing sync; chunk-0 pre-issue into buffer 0 is WAR-safe
    // (buffer 0 last read at chunk CH-2, fenced by the top-of-chunk sync).
}

__global__ void __launch_bounds__(NTHR, 1) dgm_mma_kernel(
    const float* __restrict__ x, const float* __restrict__ t,
    const float* __restrict__ Sw_b,
    const float* __restrict__ Uz_b, const float* __restrict__ Wsz_b,
    const float* __restrict__ Ug_b, const float* __restrict__ Wsg_b,
    const float* __restrict__ Ur_b, const float* __restrict__ Wsr_b,
    const float* __restrict__ Uh_b, const float* __restrict__ Wsh_b,
    const float* __restrict__ Wf_w, const float* __restrict__ Wf_b,
    const int* __restrict__ n_layers_p, float* __restrict__ out) {
    extern __shared__ char smem[];
    const int tid = threadIdx.x;
    const int lane = tid & 31;
    const int warp = tid >> 5;
    const int wm = warp >> 2;   // 0..3 (m32 group over 128 rows)
    const int wn = warp & 3;    // 0..3 (n32 group)
    const int row0 = blockIdx.x * TM;
    const uint32_t sbase = smem_u32(smem);

    // A ldmatrix lane addresses (hi; lo at +S_TILE)
    const uint32_t aS0 =
        sbase + OFF_S + (wm * 32 + (lane & 15)) * LDT + ((lane >> 4) << 4);
    const uint32_t aS1 = aS0 + 16 * LDT;
    const uint32_t aSR0 = aS0 + (OFF_SR - OFF_S);
    const uint32_t aSR1 = aSR0 + 16 * LDT;
    // B lane offset within a W chunk (hi n-rows 0-127, lo 128-255; 80B rows)
    const uint32_t bBase = (wn * 32 + (lane & 7)) * 80 +
                           (((lane >> 3) & 1) << 4) +
                           ((lane & 16) ? 128 * 80 : 0);

    // epilogue fragment coords
    const int er = wm * 32 + (lane >> 2);
    const int ecq = (lane & 3) * 2;

    // chunk-0 of Sw in flight while we stage XT
    gemm_start(sbase, 0, tid);

    // ---- build XT tiles (hi|lo) in SR region ----
    {
        char* xh = smem + OFF_SR;
        const float4* x4 = reinterpret_cast<const float4*>(x);
        for (int idx = tid; idx < TM * 25; idx += NTHR) {
            int m = idx / 25, q = idx - m * 25;
            float4 v = x4[(size_t)(row0 + m) * 25 + q];
            float vv[4] = {v.x, v.y, v.z, v.w};
#pragma unroll
            for (int j = 0; j < 4; ++j) {
                uint32_t off = m * LDT + (q * 4 + j) * 2;
                __nv_bfloat16 h = __float2bfloat16(vv[j]);
                *(__nv_bfloat16*)(xh + off) = h;
                *(__nv_bfloat16*)(xh + S_TILE + off) =
                    __float2bfloat16(vv[j] - __bfloat162float(h));
            }
        }
        if (tid < TM) {
            float tv = t[row0 + tid];
            uint32_t off = tid * LDT + 100 * 2;
            __nv_bfloat16 h = __float2bfloat16(tv);
            *(__nv_bfloat16*)(xh + off) = h;
            *(__nv_bfloat16*)(xh + S_TILE + off) =
                __float2bfloat16(tv - __bfloat162float(h));
            for (int k = 101; k < 112; ++k) {
                uint32_t o = tid * LDT + k * 2;
                *(unsigned short*)(xh + o) = 0;
                *(unsigned short*)(xh + S_TILE + o) = 0;
            }
        }
    }
    // (gemm_run's internal first sync orders the XT writes)

    float acc[8][4];

    // ---- S1 = tanh(xt @ SwT + Sw_b) -> S tiles ----
    gemm_run<7>(sbase, 0, aSR0, aSR1, bBase, tid, acc);
    gemm_start(sbase, 1, tid);  // Uz chunk0 overlaps S1 epilogue
#pragma unroll
    for (int nt = 0; nt < 4; ++nt)
#pragma unroll
        for (int mf = 0; mf < 2; ++mf) {
            int c = wn * 32 + nt * 8 + ecq;
            float2 b = __ldg((const float2*)(Sw_b + c));
            uint32_t o0 = (er + mf * 16) * LDT + c * 2, o1 = o0 + 8 * LDT;
            float* a = acc[nt * 2 + mf];
            store_split(smem + OFF_S, o0, fast_tanh(a[0] + b.x),
                        fast_tanh(a[1] + b.y));
            store_split(smem + OFF_S, o1, fast_tanh(a[2] + b.x),
                        fast_tanh(a[3] + b.y));
        }

    // ---- u planes (bias-folded) -> g_u ----
#pragma unroll 1
    for (int pl = 0; pl < 4; ++pl) {
        gemm_run<7>(sbase, pl + 1, aSR0, aSR1, bBase, tid, acc);
        gemm_start(sbase, pl < 3 ? pl + 2 : 7, tid);  // next U / first Wsr
        const float *b1p, *b2p;
        if (pl == 0)      { b1p = Uz_b; b2p = Wsz_b; }
        else if (pl == 1) { b1p = Ug_b; b2p = Wsg_b; }
        else if (pl == 2) { b1p = Ur_b; b2p = Wsr_b; }
        else              { b1p = Uh_b; b2p = Wsh_b; }
        float* uP = g_u + ((size_t)blockIdx.x * 4 + pl) * TM * HID;
#pragma unroll
        for (int nt = 0; nt < 4; ++nt)
#pragma unroll
            for (int mf = 0; mf < 2; ++mf) {
                int r = er + mf * 16, c = wn * 32 + nt * 8 + ecq;
                float2 b1 = __ldg((const float2*)(b1p + c));
                float2 b2 = __ldg((const float2*)(b2p + c));
                float* a = acc[nt * 2 + mf];
                *(float2*)(uP + r * HID + c) =
                    make_float2(a[0] + b1.x + b2.x, a[1] + b1.y + b2.y);
                *(float2*)(uP + (r + 8) * HID + c) =
                    make_float2(a[2] + b1.x + b2.x, a[3] + b1.y + b2.y);
            }
    }

    const int nl = *n_layers_p;
    const float* uZ = g_u + ((size_t)blockIdx.x * 4 + 0) * TM * HID;
    const float* uG = g_u + ((size_t)blockIdx.x * 4 + 1) * TM * HID;
    const float* uR = g_u + ((size_t)blockIdx.x * 4 + 2) * TM * HID;
    const float* uH = g_u + ((size_t)blockIdx.x * 4 + 3) * TM * HID;

    float zs[8][4];

#pragma unroll 1
    for (int l = 1; l < nl; ++l) {
        // ---- R: SR = S * tanh(uR + S@WsrT) ----
        gemm_run<8>(sbase, 7, aS0, aS1, bBase, tid, acc);
        gemm_start(sbase, 5, tid);  // Wsz chunk0 overlaps R epilogue
#pragma unroll
        for (int nt = 0; nt < 4; ++nt)
#pragma unroll
            for (int mf = 0; mf < 2; ++mf) {
                int r = er + mf * 16, c = wn * 32 + nt * 8 + ecq;
                float2 u0 = *(const float2*)(uR + r * HID + c);
                float2 u1 = *(const float2*)(uR + (r + 8) * HID + c);
                uint32_t o0 = r * LDT + c * 2, o1 = o0 + 8 * LDT;
                float2 s0 = ld_pair(smem + OFF_S, o0);
                float2 s1 = ld_pair(smem + OFF_S, o1);
                float* a = acc[nt * 2 + mf];
                store_split(smem + OFF_SR, o0, s0.x * fast_tanh(a[0] + u0.x),
                            s0.y * fast_tanh(a[1] + u0.y));
                store_split(smem + OFF_SR, o1, s1.x * fast_tanh(a[2] + u1.x),
                            s1.y * fast_tanh(a[3] + u1.y));
            }

        // ---- Z: zs = tanh(uZ + S@WszT) * S (registers) ----
        gemm_run<8>(sbase, 5, aS0, aS1, bBase, tid, acc);
        gemm_start(sbase, 6, tid);  // Wsg
#pragma unroll
        for (int nt = 0; nt < 4; ++nt)
#pragma unroll
            for (int mf = 0; mf < 2; ++mf) {
                int r = er + mf * 16, c = wn * 32 + nt * 8 + ecq;
                float2 u0 = *(const float2*)(uZ + r * HID + c);
                float2 u1 = *(const float2*)(uZ + (r + 8) * HID + c);
                uint32_t o0 = r * LDT + c * 2, o1 = o0 + 8 * LDT;
                float2 s0 = ld_pair(smem + OFF_S, o0);
                float2 s1 = ld_pair(smem + OFF_S, o1);
                float* a = acc[nt * 2 + mf];
                float* z = zs[nt * 2 + mf];
                z[0] = fast_tanh(a[0] + u0.x) * s0.x;
                z[1] = fast_tanh(a[1] + u0.y) * s0.y;
                z[2] = fast_tanh(a[2] + u1.x) * s1.x;
                z[3] = fast_tanh(a[3] + u1.y) * s1.y;
            }

        // ---- G: G = tanh(uG + S@WsgT) -> parked in (now dead) S tiles ----
        gemm_run<8>(sbase, 6, aS0, aS1, bBase, tid, acc);
        gemm_start(sbase, 8, tid);  // Wsh
        __syncthreads();  // all warps done reading S before overwriting
#pragma unroll
        for (int nt = 0; nt < 4; ++nt)
#pragma unroll
            for (int mf = 0; mf < 2; ++mf) {
                int r = er + mf * 16, c = wn * 32 + nt * 8 + ecq;
                float2 u0 = *(const float2*)(uG + r * HID + c);
                float2 u1 = *(const float2*)(uG + (r + 8) * HID + c);
                uint32_t o0 = r * LDT + c * 2, o1 = o0 + 8 * LDT;
                float* a = acc[nt * 2 + mf];
                store_split(smem + OFF_S, o0, fast_tanh(a[0] + u0.x),
                            fast_tanh(a[1] + u0.y));
                store_split(smem + OFF_S, o1, fast_tanh(a[2] + u1.x),
                            fast_tanh(a[3] + u1.y));
            }

        // ---- H: S_new = (1-G)*(uH + SR@WshT) + zs -> S tiles (own cells) ----
        gemm_run<8>(sbase, 8, aSR0, aSR1, bBase, tid, acc);
        if (l + 1 < nl) gemm_start(sbase, 7, tid);  // next layer's Wsr
#pragma unroll
        for (int nt = 0; nt < 4; ++nt)
#pragma unroll
            for (int mf = 0; mf < 2; ++mf) {
                int r = er + mf * 16, c = wn * 32 + nt * 8 + ecq;
                float2 u0 = *(const float2*)(uH + r * HID + c);
                float2 u1 = *(const float2*)(uH + (r + 8) * HID + c);
                uint32_t o0 = r * LDT + c * 2, o1 = o0 + 8 * LDT;
                float2 g0 = ld_pair(smem + OFF_S, o0);
                float2 g1 = ld_pair(smem + OFF_S, o1);
                float* a = acc[nt * 2 + mf];
                float* z = zs[nt * 2 + mf];
                store_split(smem + OFF_S, o0,
                            (1.0f - g0.x) * (a[0] + u0.x) + z[0],
                            (1.0f - g0.y) * (a[1] + u0.y) + z[1]);
                store_split(smem + OFF_S, o1,
                            (1.0f - g1.x) * (a[2] + u1.x) + z[2],
                            (1.0f - g1.y) * (a[3] + u1.y) + z[3]);
            }
        // next gemm_run's internal first sync orders these writes
    }

    // ---- final: out = S @ Wf + bf (4 threads per row, shfl reduce) ----
    __syncthreads();
    {
        const int orow = tid >> 2, q = tid & 3;  // 512 thr = 128 rows x 4
        float s = 0.0f;
#pragma unroll 4
        for (int cc = 0; cc < 16; ++cc) {
            int col = q * 32 + cc * 2;
            float2 sv = ld_pair(smem + OFF_S, orow * LDT + col * 2);
            float2 wf = __ldg((const float2*)(Wf_w + col));
            s += sv.x * wf.x + sv.y * wf.y;
        }
        s += __shfl_xor_sync(0xFFFFFFFFu, s, 1);
        s += __shfl_xor_sync(0xFFFFFFFFu, s, 2);
        if (q == 0) out[row0 + orow] = s + Wf_b[0];
    }
}

extern "C" void kernel_launch(void* const* d_in, const int* in_sizes, int n_in,
                              void* d_out, int out_size) {
    const float* x     = (const float*)d_in[0];
    const float* t     = (const float*)d_in[1];
    const float* Sw_w  = (const float*)d_in[2];
    const float* Sw_b  = (const float*)d_in[3];
    const float* Uz_w  = (const float*)d_in[4];
    const float* Uz_b  = (const float*)d_in[5];
    const float* Wsz_w = (const float*)d_in[6];
    const float* Wsz_b = (const float*)d_in[7];
    const float* Ug_w  = (const float*)d_in[8];
    const float* Ug_b  = (const float*)d_in[9];
    const float* Wsg_w = (const float*)d_in[10];
    const float* Wsg_b = (const float*)d_in[11];
    const float* Ur_w  = (const float*)d_in[12];
    const float* Ur_b  = (const float*)d_in[13];
    const float* Wsr_w = (const float*)d_in[14];
    const float* Wsr_b = (const float*)d_in[15];
    const float* Uh_w  = (const float*)d_in[16];
    const float* Uh_b  = (const float*)d_in[17];
    const float* Wsh_w = (const float*)d_in[18];
    const float* Wsh_b = (const float*)d_in[19];
    const float* Wf_w  = (const float*)d_in[20];
    const float* Wf_b  = (const float*)d_in[21];
    const int*   nlp   = (const int*)d_in[22];
    float* out = (float*)d_out;

    static bool attr_set = false;
    if (!attr_set) {
        cudaFuncSetAttribute(dgm_mma_kernel,
                             cudaFuncAttributeMaxDynamicSharedMemorySize,
                             SMEM_TOTAL);
        attr_set = true;
    }
    prep_weights<<<9, 256>>>(Sw_w, Uz_w, Ug_w, Ur_w, Uh_w,
                             Wsz_w, Wsg_w, Wsr_w, Wsh_w);
    dgm_mma_kernel<<<NBLK, NTHR, SMEM_TOTAL>>>(
        x, t, Sw_b, Uz_b, Wsz_b, Ug_b, Wsg_b, Ur_b, Wsr_b, Uh_b, Wsh_b,
        Wf_w, Wf_b, nlp, out);
}